// round 13
// baseline (speedup 1.0000x reference)
#include <cuda_runtime.h>
#include <cuda_bf16.h>
#include <cstdint>

// Path signature, truncation level 4.
// path: (B=128, S=512, D=8) fp32 -> out: (B, 8+64+512+4096 = 4680) fp32
//
// One CTA per batch, 512 threads; thread m owns (i,j,k)=(m>>6,(m>>3)&7,m&7).
// Two time halves packed in f32x2 lanes (recursion only). The level-4 rank-1
// accumulation s4[m][l] = sum_t c_t[m]*dx_t[l] is offloaded to tensor cores:
// per 8-step chunk, threads store the packed coefficients c to smem; each
// warp then runs split-tf32 mma.sync.m16n8k8 (bigxbig + bigxsmall + smallxbig)
// accumulating fp32 D fragments for its 2 row-tiles x 2 halves. This removes
// the 8 rt-3 register-bank-bound facc2 per pair-step from the FMA pipe.

#define SD 512
#define DD 8
#define HT 256                  // steps per half
#define TRS 516                 // stream table row stride (floats)
#define NCHUNK 32               // 256 steps / 8 per chunk
#define CROW 9                  // c-staging row stride (conflict-free)
#define OUT_PER_B 4680

// smem layout (floats)
#define STRMF 0                 // 8 * 516 = 4128
#define CSMA  4128              // 2 bufs * 512 * 9 = 9216
#define CSMB  13344             // 9216
#define SMEMF 22560
#define SMEMB (SMEMF * 4)       // 90240 bytes -> dynamic smem

typedef unsigned long long u64;

__device__ __forceinline__ u64 dup2(float x) {
    u64 r; asm("mov.b64 %0, {%1, %1};" : "=l"(r) : "f"(x)); return r;
}
__device__ __forceinline__ u64 fmul2(u64 a, u64 b) {
    u64 r; asm("mul.rn.f32x2 %0, %1, %2;" : "=l"(r) : "l"(a), "l"(b)); return r;
}
__device__ __forceinline__ u64 fadd2(u64 a, u64 b) {
    u64 r; asm("add.rn.f32x2 %0, %1, %2;" : "=l"(r) : "l"(a), "l"(b)); return r;
}
__device__ __forceinline__ u64 ffma2(u64 a, u64 b, u64 c) {
    u64 r; asm("fma.rn.f32x2 %0, %1, %2, %3;" : "=l"(r) : "l"(a), "l"(b), "l"(c)); return r;
}
__device__ __forceinline__ float lo2(u64 a) {
    float l, h; asm("mov.b64 {%0, %1}, %2;" : "=f"(l), "=f"(h) : "l"(a)); return l;
}
__device__ __forceinline__ float hi2(u64 a) {
    float l, h; asm("mov.b64 {%0, %1}, %2;" : "=f"(l), "=f"(h) : "l"(a)); return h;
}

// Split fp32 into tf32-big (mantissa truncation, valid tf32 bit pattern) and
// tf32-small. Dropped small*small term ~ 1e-6 relative.
__device__ __forceinline__ void tf32_split(float f, uint32_t& big, uint32_t& sml) {
    uint32_t bu = __float_as_uint(f) & 0xFFFFE000u;
    big = bu;
    float sf = f - __uint_as_float(bu);
    sml = __float_as_uint(sf) & 0xFFFFE000u;
}

__device__ __forceinline__ void mma8(float* d, const uint32_t* a, const uint32_t* b) {
    asm volatile(
        "mma.sync.aligned.m16n8k8.row.col.f32.tf32.tf32.f32 "
        "{%0,%1,%2,%3},{%4,%5,%6,%7},{%8,%9},{%0,%1,%2,%3};"
        : "+f"(d[0]), "+f"(d[1]), "+f"(d[2]), "+f"(d[3])
        : "r"(a[0]), "r"(a[1]), "r"(a[2]), "r"(a[3]), "r"(b[0]), "r"(b[1]));
}

__global__ __launch_bounds__(512, 1)
void signature_kernel(const float* __restrict__ path, float* __restrict__ out)
{
    extern __shared__ __align__(16) float sm[];

    const int b = blockIdx.x;
    const int m = threadIdx.x;            // 0..511
    const int lane = m & 31;
    const int wid  = m >> 5;              // 0..15
    const float* p = path + (size_t)b * SD * DD;

    // ---- Build pair-interleaved stream table. Thread t computes inc[t].
    {
        const int t = m;
        float r[8];
        if (t < SD - 1) {
            const float4 a0 = *(const float4*)(p + t * DD);
            const float4 a1 = *(const float4*)(p + t * DD + 4);
            const float4 c0 = *(const float4*)(p + (t + 1) * DD);
            const float4 c1 = *(const float4*)(p + (t + 1) * DD + 4);
            r[0]=c0.x-a0.x; r[1]=c0.y-a0.y; r[2]=c0.z-a0.z; r[3]=c0.w-a0.w;
            r[4]=c1.x-a1.x; r[5]=c1.y-a1.y; r[6]=c1.z-a1.z; r[7]=c1.w-a1.w;
        } else {
            #pragma unroll
            for (int d = 0; d < 8; ++d) r[d] = 0.f;   // pad: exp(0)=identity
        }
        const int tp = t & (HT - 1);      // step within half
        const int sl = t >> 8;            // 0 = half A (lo), 1 = half B (hi)
        #pragma unroll
        for (int d = 0; d < 8; ++d)
            sm[STRMF + d * TRS + tp * 2 + sl] = r[d];
    }
    __syncthreads();

    const int i = m >> 6;
    const int j = (m >> 3) & 7;
    const int k = m & 7;
    const int m9 = m * CROW;

    u64 s1 = 0ull, s2 = 0ull, s3 = 0ull;

    const u64 C24 = dup2(1.f / 24.f);
    const u64 C6  = dup2(1.f / 6.f);
    const u64 CH  = dup2(0.5f);
    const u64 C3  = dup2(3.f);

    const float* __restrict__ strm = sm + STRMF;
    const float* __restrict__ pI = strm + i * TRS;
    const float* __restrict__ pJ = strm + j * TRS;
    const float* __restrict__ pK = strm + k * TRS;

    // mma D accumulators: [tile][4] per half. Warp wid owns row tiles 2w,2w+1.
    float dA[2][4], dB[2][4];
    #pragma unroll
    for (int t0 = 0; t0 < 2; ++t0)
        #pragma unroll
        for (int q = 0; q < 4; ++q) { dA[t0][q] = 0.f; dB[t0][q] = 0.f; }

    const int kg = lane >> 2;             // mma groupID (row off / n col)
    const int kt = lane & 3;              // mma thread-in-group (k index)

#define STEPC(DI, DJ, DK, TC_, CBA, CBB) do {                                 \
    const u64 h  = fmul2((DJ), (DK));                                         \
    const u64 t1 = fmul2((DI), C24);                                          \
    const u64 t2 = ffma2(s1, C6, t1);                                         \
    const u64 c0 = ffma2(h, t2, s3);                                          \
    const u64 u  = fmul2(s2, (DK));                                           \
    const u64 c  = ffma2(u, CH, c0);                                          \
    const u64 g3 = ffma2(t2, C3, t1);   /* = s1/2 + dxi/6 */                  \
    s3 = ffma2(h, g3, fadd2(s3, u));                                          \
    s2 = ffma2((DJ), ffma2((DI), CH, s1), s2);                                \
    s1 = fadd2(s1, (DI));                                                     \
    (CBA)[m9 + (TC_)] = lo2(c);                                               \
    (CBB)[m9 + (TC_)] = hi2(c);                                               \
} while (0)

    #pragma unroll 1
    for (int ch = 0; ch < NCHUNK; ++ch) {
        float* cbufA = sm + CSMA + (ch & 1) * 4608;
        float* cbufB = sm + CSMB + (ch & 1) * 4608;

        // ---- recursion: 8 steps (both halves packed), store c to staging
        #pragma unroll
        for (int q = 0; q < 4; ++q) {
            const int g = ch * 4 + q;
            const ulonglong2 di = *(const ulonglong2*)(pI + g * 4);
            const ulonglong2 dj = *(const ulonglong2*)(pJ + g * 4);
            const ulonglong2 dk = *(const ulonglong2*)(pK + g * 4);
            STEPC(di.x, dj.x, dk.x, 2 * q,     cbufA, cbufB);
            STEPC(di.y, dj.y, dk.y, 2 * q + 1, cbufA, cbufB);
        }
        __syncthreads();

        // ---- mma phase: B fragments (dx) for this chunk, both halves
        const int tb = ch * 8 + kt;
        const float b0A = strm[kg * TRS + tb * 2];
        const float b1A = strm[kg * TRS + (tb + 4) * 2];
        const float b0B = strm[kg * TRS + tb * 2 + 1];
        const float b1B = strm[kg * TRS + (tb + 4) * 2 + 1];
        uint32_t BbA[2], BsA[2], BbB[2], BsB[2];
        tf32_split(b0A, BbA[0], BsA[0]);
        tf32_split(b1A, BbA[1], BsA[1]);
        tf32_split(b0B, BbB[0], BsB[0]);
        tf32_split(b1B, BbB[1], BsB[1]);

        #pragma unroll
        for (int tile = 0; tile < 2; ++tile) {
            const int r0 = (wid * 2 + tile) * 16 + kg;
            // half A
            {
                const float a0 = cbufA[r0 * CROW + kt];
                const float a1 = cbufA[(r0 + 8) * CROW + kt];
                const float a2 = cbufA[r0 * CROW + kt + 4];
                const float a3 = cbufA[(r0 + 8) * CROW + kt + 4];
                uint32_t Ab[4], As[4];
                tf32_split(a0, Ab[0], As[0]);
                tf32_split(a1, Ab[1], As[1]);
                tf32_split(a2, Ab[2], As[2]);
                tf32_split(a3, Ab[3], As[3]);
                mma8(dA[tile], Ab, BbA);
                mma8(dA[tile], Ab, BsA);
                mma8(dA[tile], As, BbA);
            }
            // half B
            {
                const float a0 = cbufB[r0 * CROW + kt];
                const float a1 = cbufB[(r0 + 8) * CROW + kt];
                const float a2 = cbufB[r0 * CROW + kt + 4];
                const float a3 = cbufB[(r0 + 8) * CROW + kt + 4];
                uint32_t Ab[4], As[4];
                tf32_split(a0, Ab[0], As[0]);
                tf32_split(a1, Ab[1], As[1]);
                tf32_split(a2, Ab[2], As[2]);
                tf32_split(a3, Ab[3], As[3]);
                mma8(dB[tile], Ab, BbB);
                mma8(dB[tile], Ab, BsB);
                mma8(dB[tile], As, BbB);
            }
        }
    }
#undef STEPC

    __syncthreads();   // all mma done before staging regions are repurposed

    // ---- Spill D fragments to s4 planes; store half-B small levels.
    float* planeA = sm + CSMA;            // 512 x 8, stride 8
    float* planeB = sm + CSMB;
    float* b3s = sm + CSMB + 4096;        // 512
    float* b2s = sm + CSMB + 4608;        // 64
    float* b1s = sm + CSMB + 4672;        // 8

    {
        const int c0 = kt * 2;
        #pragma unroll
        for (int tile = 0; tile < 2; ++tile) {
            const int r0 = (wid * 2 + tile) * 16 + kg;
            *(float2*)(planeA + r0 * 8 + c0)       = make_float2(dA[tile][0], dA[tile][1]);
            *(float2*)(planeA + (r0 + 8) * 8 + c0) = make_float2(dA[tile][2], dA[tile][3]);
            *(float2*)(planeB + r0 * 8 + c0)       = make_float2(dB[tile][0], dB[tile][1]);
            *(float2*)(planeB + (r0 + 8) * 8 + c0) = make_float2(dB[tile][2], dB[tile][3]);
        }
    }
    b3s[m] = hi2(s3);
    if (k == 0)        b2s[m >> 3] = hi2(s2);
    if ((m & 63) == 0) b1s[i]      = hi2(s1);
    __syncthreads();

    // ---- Chen combine: S = A (x) B.
    const float a1v = lo2(s1), a2v = lo2(s2), a3v = lo2(s3);
    float a4[8];
    {
        const float4 w0 = *(const float4*)(planeA + m * 8);
        const float4 w1 = *(const float4*)(planeA + m * 8 + 4);
        a4[0]=w0.x; a4[1]=w0.y; a4[2]=w0.z; a4[3]=w0.w;
        a4[4]=w1.x; a4[5]=w1.y; a4[6]=w1.z; a4[7]=w1.w;
    }

    float bb1[8];
    #pragma unroll
    for (int l = 0; l < 8; ++l) bb1[l] = b1s[l];
    const float4 q0 = *(const float4*)(b2s + k * 8);
    const float4 q1 = *(const float4*)(b2s + k * 8 + 4);
    const float b2kl[8] = {q0.x,q0.y,q0.z,q0.w,q1.x,q1.y,q1.z,q1.w};
    const float b2jk = b2s[j * 8 + k];
    const float4 r0v = *(const float4*)(b3s + j * 64 + k * 8);
    const float4 r1v = *(const float4*)(b3s + j * 64 + k * 8 + 4);
    const float b3jkl[8] = {r0v.x,r0v.y,r0v.z,r0v.w,r1v.x,r1v.y,r1v.z,r1v.w};
    const float4 w0 = *(const float4*)(planeB + m * 8);
    const float4 w1 = *(const float4*)(planeB + m * 8 + 4);
    const float b4m[8] = {w0.x,w0.y,w0.z,w0.w,w1.x,w1.y,w1.z,w1.w};
    const float bb3m = b3s[m];

    float r4[8];
    #pragma unroll
    for (int l = 0; l < 8; ++l) {
        float acc = a4[l] + b4m[l];
        acc = fmaf(a3v, bb1[l],   acc);
        acc = fmaf(a2v, b2kl[l],  acc);
        acc = fmaf(a1v, b3jkl[l], acc);
        r4[l] = acc;
    }
    float r3 = a3v + bb3m;
    r3 = fmaf(a2v, bb1[k], r3);
    r3 = fmaf(a1v, b2jk,  r3);
    float r2 = a2v + b2s[m >> 3];
    r2 = fmaf(a1v, bb1[j], r2);
    const float r1s = a1v + bb1[i];

    // ---- Emit: [s1(8) | s2(64) | s3(512) | s4(4096)] per batch.
    float* ob = out + (size_t)b * OUT_PER_B;
    float4* o4 = (float4*)(ob + 8 + 64 + 512 + m * 8);
    o4[0] = make_float4(r4[0], r4[1], r4[2], r4[3]);
    o4[1] = make_float4(r4[4], r4[5], r4[6], r4[7]);
    ob[8 + 64 + m] = r3;
    if (k == 0)        ob[8 + (m >> 3)] = r2;
    if ((m & 63) == 0) ob[m >> 6]       = r1s;
}

extern "C" void kernel_launch(void* const* d_in, const int* in_sizes, int n_in,
                              void* d_out, int out_size)
{
    const float* path = (const float*)d_in[0];
    float* out = (float*)d_out;
    const int nb = in_sizes[0] / (SD * DD);   // 128
    cudaFuncSetAttribute(signature_kernel,
                         cudaFuncAttributeMaxDynamicSharedMemorySize, SMEMB);
    signature_kernel<<<nb, 512, SMEMB>>>(path, out);
}

// round 14
// speedup vs baseline: 1.1450x; 1.1450x over previous
#include <cuda_runtime.h>
#include <cuda_bf16.h>
#include <cstdint>

// Path signature, truncation level 4.
// path: (B=128, S=512, D=8) fp32 -> out: (B, 8+64+512+4096 = 4680) fp32
//
// One CTA per batch, 512 threads; thread m owns (i,j,k)=(m>>6,(m>>3)&7,m&7).
// Two time halves packed in f32x2 lanes (recursion). Level-4 accumulation
// s4[m][l] = sum_t c_t[m]*dx_t[l] runs on tensor cores via split-tf32
// mma.sync.m16n8k8 (big*big + big*small + small*big).
//
// KEY CHANGE vs R13: warp w's mma tiles are rows 32w..32w+31 = its OWN
// threads' m values, so c-staging is warp-local -> all per-chunk
// __syncthreads replaced by __syncwarp (no cross-warp coupling), staging
// single-buffered. dx big/small tf32 tables are pre-split once at setup.

#define SD 512
#define DD 8
#define HT 256                  // steps per half
#define TRS 516                 // table row stride (floats)
#define NCHUNK 32               // 256 steps / 8 per chunk
#define CROW 9                  // c-staging row stride (conflict-free)
#define OUT_PER_B 4680

// smem layout (floats)
#define STRMF 0                 // full-precision streams: 8*516 = 4128
#define BBIG  4128              // tf32-big dx table:      4128
#define BSML  8256              // tf32-small dx table:    4128
#define CSA   12384             // c staging half A: 512*9 = 4608
#define CSB   16992             // c staging half B: 4608
#define SMEMF 21600
#define SMEMB (SMEMF * 4)       // 86400 bytes -> dynamic smem

typedef unsigned long long u64;

__device__ __forceinline__ u64 dup2(float x) {
    u64 r; asm("mov.b64 %0, {%1, %1};" : "=l"(r) : "f"(x)); return r;
}
__device__ __forceinline__ u64 fmul2(u64 a, u64 b) {
    u64 r; asm("mul.rn.f32x2 %0, %1, %2;" : "=l"(r) : "l"(a), "l"(b)); return r;
}
__device__ __forceinline__ u64 fadd2(u64 a, u64 b) {
    u64 r; asm("add.rn.f32x2 %0, %1, %2;" : "=l"(r) : "l"(a), "l"(b)); return r;
}
__device__ __forceinline__ u64 ffma2(u64 a, u64 b, u64 c) {
    u64 r; asm("fma.rn.f32x2 %0, %1, %2, %3;" : "=l"(r) : "l"(a), "l"(b), "l"(c)); return r;
}
__device__ __forceinline__ float lo2(u64 a) {
    float l, h; asm("mov.b64 {%0, %1}, %2;" : "=f"(l), "=f"(h) : "l"(a)); return l;
}
__device__ __forceinline__ float hi2(u64 a) {
    float l, h; asm("mov.b64 {%0, %1}, %2;" : "=f"(l), "=f"(h) : "l"(a)); return h;
}

__device__ __forceinline__ void tf32_split(float f, uint32_t& big, uint32_t& sml) {
    uint32_t bu = __float_as_uint(f) & 0xFFFFE000u;
    big = bu;
    float sf = f - __uint_as_float(bu);
    sml = __float_as_uint(sf) & 0xFFFFE000u;
}

__device__ __forceinline__ void mma8(float* d, const uint32_t* a, const uint32_t* b) {
    asm volatile(
        "mma.sync.aligned.m16n8k8.row.col.f32.tf32.tf32.f32 "
        "{%0,%1,%2,%3},{%4,%5,%6,%7},{%8,%9},{%0,%1,%2,%3};"
        : "+f"(d[0]), "+f"(d[1]), "+f"(d[2]), "+f"(d[3])
        : "r"(a[0]), "r"(a[1]), "r"(a[2]), "r"(a[3]), "r"(b[0]), "r"(b[1]));
}

__global__ __launch_bounds__(512, 1)
void signature_kernel(const float* __restrict__ path, float* __restrict__ out)
{
    extern __shared__ __align__(16) float sm[];

    const int b = blockIdx.x;
    const int m = threadIdx.x;            // 0..511
    const int lane = m & 31;
    const int wid  = m >> 5;              // 0..15
    const float* p = path + (size_t)b * SD * DD;

    // ---- Build stream table + pre-split tf32 big/small dx tables.
    {
        const int t = m;
        float r[8];
        if (t < SD - 1) {
            const float4 a0 = *(const float4*)(p + t * DD);
            const float4 a1 = *(const float4*)(p + t * DD + 4);
            const float4 c0 = *(const float4*)(p + (t + 1) * DD);
            const float4 c1 = *(const float4*)(p + (t + 1) * DD + 4);
            r[0]=c0.x-a0.x; r[1]=c0.y-a0.y; r[2]=c0.z-a0.z; r[3]=c0.w-a0.w;
            r[4]=c1.x-a1.x; r[5]=c1.y-a1.y; r[6]=c1.z-a1.z; r[7]=c1.w-a1.w;
        } else {
            #pragma unroll
            for (int d = 0; d < 8; ++d) r[d] = 0.f;   // pad: exp(0)=identity
        }
        const int tp = t & (HT - 1);      // step within half
        const int sl = t >> 8;            // 0 = half A (lo), 1 = half B (hi)
        #pragma unroll
        for (int d = 0; d < 8; ++d) {
            sm[STRMF + d * TRS + tp * 2 + sl] = r[d];
            uint32_t bg, sl2;
            tf32_split(r[d], bg, sl2);
            sm[BBIG + d * TRS + tp * 2 + sl] = __uint_as_float(bg);
            sm[BSML + d * TRS + tp * 2 + sl] = __uint_as_float(sl2);
        }
    }
    __syncthreads();

    const int i = m >> 6;
    const int j = (m >> 3) & 7;
    const int k = m & 7;
    const int m9 = m * CROW;

    u64 s1 = 0ull, s2 = 0ull, s3 = 0ull;

    const u64 C24 = dup2(1.f / 24.f);
    const u64 C6  = dup2(1.f / 6.f);
    const u64 CH  = dup2(0.5f);
    const u64 C3  = dup2(3.f);

    const float* __restrict__ strm = sm + STRMF;
    const float* __restrict__ pI = strm + i * TRS;
    const float* __restrict__ pJ = strm + j * TRS;
    const float* __restrict__ pK = strm + k * TRS;
    float* __restrict__ cbufA = sm + CSA;
    float* __restrict__ cbufB = sm + CSB;

    // mma D accumulators: [tile][4] per half. Warp wid owns rows 32w..32w+31.
    float dA[2][4], dB[2][4];
    #pragma unroll
    for (int t0 = 0; t0 < 2; ++t0)
        #pragma unroll
        for (int q = 0; q < 4; ++q) { dA[t0][q] = 0.f; dB[t0][q] = 0.f; }

    const int kg = lane >> 2;             // mma groupID
    const int kt = lane & 3;              // mma thread-in-group

#define STEPC(DI, DJ, DK, TC_) do {                                           \
    const u64 h  = fmul2((DJ), (DK));                                         \
    const u64 t1 = fmul2((DI), C24);                                          \
    const u64 t2 = ffma2(s1, C6, t1);                                         \
    const u64 c0 = ffma2(h, t2, s3);                                          \
    const u64 u  = fmul2(s2, (DK));                                           \
    const u64 c  = ffma2(u, CH, c0);                                          \
    const u64 g3 = ffma2(t2, C3, t1);   /* = s1/2 + dxi/6 */                  \
    s3 = ffma2(h, g3, fadd2(s3, u));                                          \
    s2 = ffma2((DJ), ffma2((DI), CH, s1), s2);                                \
    s1 = fadd2(s1, (DI));                                                     \
    cbufA[m9 + (TC_)] = lo2(c);                                               \
    cbufB[m9 + (TC_)] = hi2(c);                                               \
} while (0)

    #pragma unroll 1
    for (int ch = 0; ch < NCHUNK; ++ch) {
        // ---- recursion: 8 steps (both halves packed), stage c (warp-local)
        #pragma unroll
        for (int q = 0; q < 4; ++q) {
            const int g = ch * 4 + q;
            const ulonglong2 di = *(const ulonglong2*)(pI + g * 4);
            const ulonglong2 dj = *(const ulonglong2*)(pJ + g * 4);
            const ulonglong2 dk = *(const ulonglong2*)(pK + g * 4);
            STEPC(di.x, dj.x, dk.x, 2 * q);
            STEPC(di.y, dj.y, dk.y, 2 * q + 1);
        }
        __syncwarp();   // staging rows 32w..32w+31 written by this warp only

        // ---- mma phase: B fragments from pre-split tables
        const int tb = ch * 8 + kt;
        uint32_t BbA[2], BsA[2], BbB[2], BsB[2];
        BbA[0] = __float_as_uint(sm[BBIG + kg * TRS + tb * 2]);
        BbA[1] = __float_as_uint(sm[BBIG + kg * TRS + (tb + 4) * 2]);
        BsA[0] = __float_as_uint(sm[BSML + kg * TRS + tb * 2]);
        BsA[1] = __float_as_uint(sm[BSML + kg * TRS + (tb + 4) * 2]);
        BbB[0] = __float_as_uint(sm[BBIG + kg * TRS + tb * 2 + 1]);
        BbB[1] = __float_as_uint(sm[BBIG + kg * TRS + (tb + 4) * 2 + 1]);
        BsB[0] = __float_as_uint(sm[BSML + kg * TRS + tb * 2 + 1]);
        BsB[1] = __float_as_uint(sm[BSML + kg * TRS + (tb + 4) * 2 + 1]);

        #pragma unroll
        for (int tile = 0; tile < 2; ++tile) {
            const int r0 = (wid * 2 + tile) * 16 + kg;   // in [32w, 32w+31]
            {   // half A
                const float a0 = cbufA[r0 * CROW + kt];
                const float a1 = cbufA[(r0 + 8) * CROW + kt];
                const float a2 = cbufA[r0 * CROW + kt + 4];
                const float a3 = cbufA[(r0 + 8) * CROW + kt + 4];
                uint32_t Ab[4], As[4];
                tf32_split(a0, Ab[0], As[0]);
                tf32_split(a1, Ab[1], As[1]);
                tf32_split(a2, Ab[2], As[2]);
                tf32_split(a3, Ab[3], As[3]);
                mma8(dA[tile], Ab, BbA);
                mma8(dA[tile], Ab, BsA);
                mma8(dA[tile], As, BbA);
            }
            {   // half B
                const float a0 = cbufB[r0 * CROW + kt];
                const float a1 = cbufB[(r0 + 8) * CROW + kt];
                const float a2 = cbufB[r0 * CROW + kt + 4];
                const float a3 = cbufB[(r0 + 8) * CROW + kt + 4];
                uint32_t Ab[4], As[4];
                tf32_split(a0, Ab[0], As[0]);
                tf32_split(a1, Ab[1], As[1]);
                tf32_split(a2, Ab[2], As[2]);
                tf32_split(a3, Ab[3], As[3]);
                mma8(dB[tile], Ab, BbB);
                mma8(dB[tile], Ab, BsB);
                mma8(dB[tile], As, BbB);
            }
        }
        __syncwarp();   // mma reads done before next chunk overwrites staging
    }
#undef STEPC

    // ---- Spill D fragments to s4 planes (warp-local rows); cross-warp
    //      levels 1-3 of half B need a full barrier before combine.
    float* planeA = sm + CSA;             // 512 x 8
    float* planeB = sm + CSB;
    float* b3s = sm + BBIG;               // 512   (dx tables dead now)
    float* b2s = sm + BBIG + 512;         // 64
    float* b1s = sm + BBIG + 576;         // 8

    __syncthreads();   // everyone past the chunk loop; staging repurposed
    {
        const int c0 = kt * 2;
        #pragma unroll
        for (int tile = 0; tile < 2; ++tile) {
            const int r0 = (wid * 2 + tile) * 16 + kg;
            *(float2*)(planeA + r0 * 8 + c0)       = make_float2(dA[tile][0], dA[tile][1]);
            *(float2*)(planeA + (r0 + 8) * 8 + c0) = make_float2(dA[tile][2], dA[tile][3]);
            *(float2*)(planeB + r0 * 8 + c0)       = make_float2(dB[tile][0], dB[tile][1]);
            *(float2*)(planeB + (r0 + 8) * 8 + c0) = make_float2(dB[tile][2], dB[tile][3]);
        }
    }
    b3s[m] = hi2(s3);
    if (k == 0)        b2s[m >> 3] = hi2(s2);
    if ((m & 63) == 0) b1s[i]      = hi2(s1);
    __syncthreads();

    // ---- Chen combine: S = A (x) B.
    const float a1v = lo2(s1), a2v = lo2(s2), a3v = lo2(s3);
    float a4[8];
    {
        const float4 w0 = *(const float4*)(planeA + m * 8);
        const float4 w1 = *(const float4*)(planeA + m * 8 + 4);
        a4[0]=w0.x; a4[1]=w0.y; a4[2]=w0.z; a4[3]=w0.w;
        a4[4]=w1.x; a4[5]=w1.y; a4[6]=w1.z; a4[7]=w1.w;
    }

    float bb1[8];
    #pragma unroll
    for (int l = 0; l < 8; ++l) bb1[l] = b1s[l];
    const float4 q0 = *(const float4*)(b2s + k * 8);
    const float4 q1 = *(const float4*)(b2s + k * 8 + 4);
    const float b2kl[8] = {q0.x,q0.y,q0.z,q0.w,q1.x,q1.y,q1.z,q1.w};
    const float b2jk = b2s[j * 8 + k];
    const float4 r0v = *(const float4*)(b3s + j * 64 + k * 8);
    const float4 r1v = *(const float4*)(b3s + j * 64 + k * 8 + 4);
    const float b3jkl[8] = {r0v.x,r0v.y,r0v.z,r0v.w,r1v.x,r1v.y,r1v.z,r1v.w};
    const float4 w0 = *(const float4*)(planeB + m * 8);
    const float4 w1 = *(const float4*)(planeB + m * 8 + 4);
    const float b4m[8] = {w0.x,w0.y,w0.z,w0.w,w1.x,w1.y,w1.z,w1.w};
    const float bb3m = b3s[m];

    float r4[8];
    #pragma unroll
    for (int l = 0; l < 8; ++l) {
        float acc = a4[l] + b4m[l];
        acc = fmaf(a3v, bb1[l],   acc);
        acc = fmaf(a2v, b2kl[l],  acc);
        acc = fmaf(a1v, b3jkl[l], acc);
        r4[l] = acc;
    }
    float r3 = a3v + bb3m;
    r3 = fmaf(a2v, bb1[k], r3);
    r3 = fmaf(a1v, b2jk,  r3);
    float r2 = a2v + b2s[m >> 3];
    r2 = fmaf(a1v, bb1[j], r2);
    const float r1s = a1v + bb1[i];

    // ---- Emit: [s1(8) | s2(64) | s3(512) | s4(4096)] per batch.
    float* ob = out + (size_t)b * OUT_PER_B;
    float4* o4 = (float4*)(ob + 8 + 64 + 512 + m * 8);
    o4[0] = make_float4(r4[0], r4[1], r4[2], r4[3]);
    o4[1] = make_float4(r4[4], r4[5], r4[6], r4[7]);
    ob[8 + 64 + m] = r3;
    if (k == 0)        ob[8 + (m >> 3)] = r2;
    if ((m & 63) == 0) ob[m >> 6]       = r1s;
}

extern "C" void kernel_launch(void* const* d_in, const int* in_sizes, int n_in,
                              void* d_out, int out_size)
{
    const float* path = (const float*)d_in[0];
    float* out = (float*)d_out;
    const int nb = in_sizes[0] / (SD * DD);   // 128
    cudaFuncSetAttribute(signature_kernel,
                         cudaFuncAttributeMaxDynamicSharedMemorySize, SMEMB);
    signature_kernel<<<nb, 512, SMEMB>>>(path, out);
}